// round 2
// baseline (speedup 1.0000x reference)
#include <cuda_runtime.h>
#include <stdint.h>

#define D 128
#define NMAX 50000
#define EMAX 600000

// Scratch (static device globals — no runtime allocation allowed).
// Referenced ONLY from device code (host code must not pass these as args).
__device__ __align__(16) float g_hs [(size_t)NMAX * D];  // (X@W) * dis[row]
__device__ __align__(16) float g_acc[(size_t)NMAX * D];  // scatter accumulator
__device__ __align__(16) float g_u  [(size_t)NMAX * D];  // post-LN/ReLU activations
__device__ float g_dis[NMAX];
__device__ int   g_deg[NMAX];

// ---------------------------------------------------------------------------
// Zero acc + deg
__global__ void k_zero(int n4, int nN) {
    int i = blockIdx.x * blockDim.x + threadIdx.x;
    if (i < n4) ((float4*)g_acc)[i] = make_float4(0.f, 0.f, 0.f, 0.f);
    if (i < nN) g_deg[i] = 0;
}

// Degree count on destination
__global__ void k_count(const int* __restrict__ dst, int nE) {
    int e = blockIdx.x * blockDim.x + threadIdx.x;
    if (e < nE) atomicAdd(&g_deg[dst[e]], 1);
}

// dis = rsqrt(deg + 1)   (self-loop)
__global__ void k_dis(int nN) {
    int i = blockIdx.x * blockDim.x + threadIdx.x;
    if (i < nN) g_dis[i] = rsqrtf((float)g_deg[i] + 1.0f);
}

// ---------------------------------------------------------------------------
// GEMM: g_hs[r, :] = (IN[r, :] @ W) * g_dis[r]
// IN = (useU ? g_u : Xext). Tile: 64 rows x 128 cols. 256 threads, 8x4 micro.
__global__ void __launch_bounds__(256) k_gemm(const float* __restrict__ Xext,
                                              const float* __restrict__ W,
                                              int nrows, int useU) {
    extern __shared__ float smem[];
    float* Ws = smem;             // 128 x 128
    float* Xs = smem + 128 * 128; // 64 x 132 (padded)

    const float* X = useU ? (const float*)g_u : Xext;

    const int tid = threadIdx.x;
    const int row0 = blockIdx.x * 64;

    // Load W (16384 floats = 4096 float4 / 256 threads = 16 each), coalesced
    {
        const float4* Wv = (const float4*)W;
        float4* Wsv = (float4*)Ws;
        #pragma unroll
        for (int i = 0; i < 16; i++) Wsv[tid + i * 256] = Wv[tid + i * 256];
    }
    // Load X tile (64 rows x 32 float4 = 2048 float4 / 256 = 8 each)
    {
        #pragma unroll
        for (int i = 0; i < 8; i++) {
            int idx = tid + i * 256;
            int r = idx >> 5;
            int c = idx & 31;
            float4 v = make_float4(0.f, 0.f, 0.f, 0.f);
            if (row0 + r < nrows) v = ((const float4*)(X + (size_t)(row0 + r) * D))[c];
            *(float4*)&Xs[r * 132 + c * 4] = v;
        }
    }
    __syncthreads();

    const int tx = tid & 31;   // cols tx*4 .. tx*4+3
    const int ty = tid >> 5;   // rows ty*8 .. ty*8+7
    float acc[8][4] = {};

    #pragma unroll 4
    for (int k = 0; k < 128; k++) {
        float4 b = *(float4*)&Ws[k * 128 + tx * 4];   // LDS.128, conflict-free
        #pragma unroll
        for (int m = 0; m < 8; m++) {
            float a = Xs[(ty * 8 + m) * 132 + k];     // warp broadcast
            acc[m][0] += a * b.x;
            acc[m][1] += a * b.y;
            acc[m][2] += a * b.z;
            acc[m][3] += a * b.w;
        }
    }

    #pragma unroll
    for (int m = 0; m < 8; m++) {
        int r = row0 + ty * 8 + m;
        if (r < nrows) {
            float s = g_dis[r];
            float4 v = make_float4(acc[m][0] * s, acc[m][1] * s,
                                   acc[m][2] * s, acc[m][3] * s);
            *(float4*)&g_hs[(size_t)r * D + tx * 4] = v;
        }
    }
}

// ---------------------------------------------------------------------------
// Scatter: one warp per edge. acc[dst] += hs[src]  (128 floats = 32 lanes x f4)
__global__ void __launch_bounds__(256) k_scatter(const int* __restrict__ src,
                                                 const int* __restrict__ dst,
                                                 int nE) {
    int idx = blockIdx.x * blockDim.x + threadIdx.x;
    int e = idx >> 5;
    if (e >= nE) return;
    int lane = idx & 31;
    int s = __ldg(&src[e]);
    int d = __ldg(&dst[e]);
    float4 v = ((const float4*)(g_hs + (size_t)s * D))[lane];
    float* ap = g_acc + (size_t)d * D + (size_t)lane * 4;
    asm volatile("red.global.add.v4.f32 [%0], {%1,%2,%3,%4};"
                 :: "l"(ap), "f"(v.x), "f"(v.y), "f"(v.z), "f"(v.w) : "memory");
}

// ---------------------------------------------------------------------------
// Finalize conv + residual + LayerNorm + ReLU (one warp per node).
// h = dis*(acc+hs)+b ; t = h + ori ; g_u = relu(LN(t)). Also resets acc to 0.
__global__ void __launch_bounds__(256) k_fin_ln(const float* __restrict__ ori,
                                                const float* __restrict__ bias,
                                                const float* __restrict__ lw,
                                                const float* __restrict__ lb,
                                                int nN) {
    int idx = blockIdx.x * blockDim.x + threadIdx.x;
    int node = idx >> 5;
    if (node >= nN) return;
    int lane = idx & 31;
    size_t base = (size_t)node * D + (size_t)lane * 4;

    float4 a  = *(float4*)(g_acc + base);
    float4 hv = *(float4*)(g_hs + base);
    *(float4*)(g_acc + base) = make_float4(0.f, 0.f, 0.f, 0.f);  // reset for next scatter
    float s = g_dis[node];
    float4 bb = *(const float4*)(bias + lane * 4);
    float4 o  = *(const float4*)(ori + base);

    float4 t;
    t.x = s * (a.x + hv.x) + bb.x + o.x;
    t.y = s * (a.y + hv.y) + bb.y + o.y;
    t.z = s * (a.z + hv.z) + bb.z + o.z;
    t.w = s * (a.w + hv.w) + bb.w + o.w;

    float sum = t.x + t.y + t.z + t.w;
    float sq  = t.x * t.x + t.y * t.y + t.z * t.z + t.w * t.w;
    #pragma unroll
    for (int off = 16; off; off >>= 1) {
        sum += __shfl_xor_sync(0xFFFFFFFFu, sum, off);
        sq  += __shfl_xor_sync(0xFFFFFFFFu, sq,  off);
    }
    float mu  = sum * (1.0f / 128.0f);
    float var = sq * (1.0f / 128.0f) - mu * mu;
    float inv = rsqrtf(var + 1e-5f);

    float4 w   = *(const float4*)(lw + lane * 4);
    float4 lbv = *(const float4*)(lb + lane * 4);
    float4 u;
    u.x = fmaxf((t.x - mu) * inv * w.x + lbv.x, 0.f);
    u.y = fmaxf((t.y - mu) * inv * w.y + lbv.y, 0.f);
    u.z = fmaxf((t.z - mu) * inv * w.z + lbv.z, 0.f);
    u.w = fmaxf((t.w - mu) * inv * w.w + lbv.w, 0.f);
    *(float4*)(g_u + base) = u;
}

// Final conv output (no LN): out = dis*(acc+hs) + b2
__global__ void __launch_bounds__(256) k_fin_out(const float* __restrict__ bias,
                                                 float* __restrict__ out, int nN) {
    int idx = blockIdx.x * blockDim.x + threadIdx.x;
    int node = idx >> 5;
    if (node >= nN) return;
    int lane = idx & 31;
    size_t base = (size_t)node * D + (size_t)lane * 4;
    float4 a  = *(float4*)(g_acc + base);
    float4 hv = *(float4*)(g_hs + base);
    float s = g_dis[node];
    float4 bb = *(const float4*)(bias + lane * 4);
    float4 r;
    r.x = s * (a.x + hv.x) + bb.x;
    r.y = s * (a.y + hv.y) + bb.y;
    r.z = s * (a.z + hv.z) + bb.z;
    r.w = s * (a.w + hv.w) + bb.w;
    *(float4*)(out + base) = r;
}

// ---------------------------------------------------------------------------
extern "C" void kernel_launch(void* const* d_in, const int* in_sizes, int n_in,
                              void* d_out, int out_size) {
    // Input-order detection: setup_inputs dict order vs reference-arg order.
    int iSrc, iDst, iW1, iB1, iW2, iB2, iL1w, iL1b, iL2w, iL2b;
    if (n_in >= 3 && in_sizes[1] == in_sizes[2] && in_sizes[1] > 100000) {
        // in_feat, edge_src, edge_dst, W1, b1, W2, b2, ln1_w, ln1_b, ln2_w, ln2_b
        iSrc = 1; iDst = 2; iW1 = 3; iB1 = 4; iW2 = 5; iB2 = 6;
        iL1w = 7; iL1b = 8; iL2w = 9; iL2b = 10;
    } else {
        // in_feat, W1, b1, W2, b2, ln1_w, ln1_b, ln2_w, ln2_b, edge_src, edge_dst
        iW1 = 1; iB1 = 2; iW2 = 3; iB2 = 4; iL1w = 5; iL1b = 6;
        iL2w = 7; iL2b = 8; iSrc = 9; iDst = 10;
    }

    const float* X   = (const float*)d_in[0];
    const int*   src = (const int*)d_in[iSrc];
    const int*   dst = (const int*)d_in[iDst];
    const float* W1  = (const float*)d_in[iW1];
    const float* b1  = (const float*)d_in[iB1];
    const float* W2  = (const float*)d_in[iW2];
    const float* b2  = (const float*)d_in[iB2];
    const float* l1w = (const float*)d_in[iL1w];
    const float* l1b = (const float*)d_in[iL1b];
    const float* l2w = (const float*)d_in[iL2w];
    const float* l2b = (const float*)d_in[iL2b];
    float* out = (float*)d_out;

    const int N = in_sizes[0] / D;
    const int E = in_sizes[iSrc];

    const int GEMM_SMEM = (128 * 128 + 64 * 132) * (int)sizeof(float); // 99328 B
    cudaFuncSetAttribute(k_gemm, cudaFuncAttributeMaxDynamicSharedMemorySize, GEMM_SMEM);

    const int T = 256;
    int zb  = (N * 32 + T - 1) / T;          // N*128/4 float4 slots
    int cb  = (E + T - 1) / T;
    int db  = (N + T - 1) / T;
    int gb  = (N + 63) / 64;
    int sb  = ((E * 32) + T - 1) / T;        // one warp per edge
    int fb  = ((N * 32) + T - 1) / T;        // one warp per node

    // deg / dis
    k_zero <<<zb, T>>>(N * 32, N);
    k_count<<<cb, T>>>(dst, E);
    k_dis  <<<db, T>>>(N);

    // conv 1 (W1, b1) + residual + LN1 + ReLU
    k_gemm   <<<gb, T, GEMM_SMEM>>>(X, W1, N, 0);
    k_scatter<<<sb, T>>>(src, dst, E);
    k_fin_ln <<<fb, T>>>(X, b1, l1w, l1b, N);

    // conv 2 (W2, b2) + residual + LN2 + ReLU
    k_gemm   <<<gb, T, GEMM_SMEM>>>(X, W2, N, 1);
    k_scatter<<<sb, T>>>(src, dst, E);
    k_fin_ln <<<fb, T>>>(X, b2, l2w, l2b, N);

    // conv 3 (W2, b2) -> output
    k_gemm   <<<gb, T, GEMM_SMEM>>>(X, W2, N, 1);
    k_scatter<<<sb, T>>>(src, dst, E);
    k_fin_out<<<fb, T>>>(b2, out, N);
}

// round 3
// speedup vs baseline: 1.5600x; 1.5600x over previous
#include <cuda_runtime.h>
#include <stdint.h>

#define D 128
#define NMAX 50000
#define EMAX 600000

// Scratch (static device globals). Referenced ONLY from device code.
__device__ __align__(16) float g_hs [(size_t)NMAX * D];  // (IN@W) * dis[row]
__device__ __align__(16) float g_u  [(size_t)NMAX * D];  // post-LN/ReLU activations
__device__ float g_dis[NMAX];
__device__ int   g_deg[NMAX];
__device__ int   g_cur[NMAX];
__device__ int   g_off[NMAX + 1];
__device__ int   g_csr[EMAX];     // incoming-edge source ids, grouped by dst

// ---------------------------------------------------------------------------
__global__ void k_zero(int nN) {
    int i = blockIdx.x * blockDim.x + threadIdx.x;
    if (i < nN) { g_deg[i] = 0; g_cur[i] = 0; }
}

__global__ void k_count(const int* __restrict__ dst, int nE) {
    int e = blockIdx.x * blockDim.x + threadIdx.x;
    if (e < nE) atomicAdd(&g_deg[dst[e]], 1);
}

__global__ void k_dis(int nN) {
    int i = blockIdx.x * blockDim.x + threadIdx.x;
    if (i < nN) g_dis[i] = rsqrtf((float)g_deg[i] + 1.0f);
}

// Exclusive prefix sum of deg -> off. Single block, 1024 threads.
__global__ void __launch_bounds__(1024) k_scan(int nN) {
    __shared__ int sums[1024];
    const int tid = threadIdx.x;
    const int chunk = (nN + 1023) / 1024;
    const int start = tid * chunk;
    const int end   = min(start + chunk, nN);

    int s = 0;
    for (int i = start; i < end; i++) s += g_deg[i];
    sums[tid] = s;
    __syncthreads();

    // Hillis-Steele inclusive scan over 1024 partials
    for (int off = 1; off < 1024; off <<= 1) {
        int t = (tid >= off) ? sums[tid - off] : 0;
        __syncthreads();
        sums[tid] += t;
        __syncthreads();
    }

    int running = (tid == 0) ? 0 : sums[tid - 1];
    for (int i = start; i < end; i++) {
        g_off[i] = running;
        running += g_deg[i];
    }
    if (end == nN && start <= nN) g_off[nN] = running;
}

// Fill CSR: for each edge, append src into dst's row.
__global__ void k_fill(const int* __restrict__ src, const int* __restrict__ dst,
                       int nE) {
    int e = blockIdx.x * blockDim.x + threadIdx.x;
    if (e >= nE) return;
    int d = dst[e];
    int pos = atomicAdd(&g_cur[d], 1);
    g_csr[g_off[d] + pos] = src[e];
}

// ---------------------------------------------------------------------------
// GEMM: g_hs[r, :] = (IN[r, :] @ W) * g_dis[r],  IN = (useU ? g_u : Xext)
__global__ void __launch_bounds__(256) k_gemm(const float* __restrict__ Xext,
                                              const float* __restrict__ W,
                                              int nrows, int useU) {
    extern __shared__ float smem[];
    float* Ws = smem;             // 128 x 128
    float* Xs = smem + 128 * 128; // 64 x 132 (padded)

    const float* X = useU ? (const float*)g_u : Xext;

    const int tid = threadIdx.x;
    const int row0 = blockIdx.x * 64;

    {
        const float4* Wv = (const float4*)W;
        float4* Wsv = (float4*)Ws;
        #pragma unroll
        for (int i = 0; i < 16; i++) Wsv[tid + i * 256] = Wv[tid + i * 256];
    }
    {
        #pragma unroll
        for (int i = 0; i < 8; i++) {
            int idx = tid + i * 256;
            int r = idx >> 5;
            int c = idx & 31;
            float4 v = make_float4(0.f, 0.f, 0.f, 0.f);
            if (row0 + r < nrows) v = ((const float4*)(X + (size_t)(row0 + r) * D))[c];
            *(float4*)&Xs[r * 132 + c * 4] = v;
        }
    }
    __syncthreads();

    const int tx = tid & 31;
    const int ty = tid >> 5;
    float acc[8][4] = {};

    #pragma unroll 4
    for (int k = 0; k < 128; k++) {
        float4 b = *(float4*)&Ws[k * 128 + tx * 4];
        #pragma unroll
        for (int m = 0; m < 8; m++) {
            float a = Xs[(ty * 8 + m) * 132 + k];
            acc[m][0] += a * b.x;
            acc[m][1] += a * b.y;
            acc[m][2] += a * b.z;
            acc[m][3] += a * b.w;
        }
    }

    #pragma unroll
    for (int m = 0; m < 8; m++) {
        int r = row0 + ty * 8 + m;
        if (r < nrows) {
            float s = g_dis[r];
            float4 v = make_float4(acc[m][0] * s, acc[m][1] * s,
                                   acc[m][2] * s, acc[m][3] * s);
            *(float4*)&g_hs[(size_t)r * D + tx * 4] = v;
        }
    }
}

// ---------------------------------------------------------------------------
// Fused gather + conv-finalize + (residual + LN + ReLU | plain output).
// One warp per node. Row accumulates in registers (lane owns 4 floats).
//   agg  = sum over incoming edges of g_hs[src]        (hs already *dis[src])
//   t    = dis[node]*(agg + g_hs[node]) + bias  [+ ori]
//   mode 0: g_u = relu(LN(t));  mode 1: out = t
__global__ void __launch_bounds__(256) k_gather(const float* __restrict__ ori,
                                                const float* __restrict__ bias,
                                                const float* __restrict__ lw,
                                                const float* __restrict__ lb,
                                                float* __restrict__ out,
                                                int nN, int mode) {
    int idx = blockIdx.x * blockDim.x + threadIdx.x;
    int node = idx >> 5;
    if (node >= nN) return;
    const int lane = idx & 31;

    const int beg = g_off[node];
    const int end = g_off[node + 1];

    float4 a = make_float4(0.f, 0.f, 0.f, 0.f);
    const float4* hs4 = (const float4*)g_hs;

    int e = beg;
    for (; e + 1 < end; e += 2) {
        int s0 = __ldg(&g_csr[e]);
        int s1 = __ldg(&g_csr[e + 1]);
        float4 v0 = hs4[(size_t)s0 * 32 + lane];
        float4 v1 = hs4[(size_t)s1 * 32 + lane];
        a.x += v0.x; a.y += v0.y; a.z += v0.z; a.w += v0.w;
        a.x += v1.x; a.y += v1.y; a.z += v1.z; a.w += v1.w;
    }
    if (e < end) {
        int s0 = __ldg(&g_csr[e]);
        float4 v0 = hs4[(size_t)s0 * 32 + lane];
        a.x += v0.x; a.y += v0.y; a.z += v0.z; a.w += v0.w;
    }

    // self-loop term: + g_hs[node] (== dis[node] * h[node])
    float4 hv = hs4[(size_t)node * 32 + lane];
    float s = g_dis[node];
    float4 bb = *(const float4*)(bias + lane * 4);

    float4 t;
    t.x = s * (a.x + hv.x) + bb.x;
    t.y = s * (a.y + hv.y) + bb.y;
    t.z = s * (a.z + hv.z) + bb.z;
    t.w = s * (a.w + hv.w) + bb.w;

    size_t base = (size_t)node * D + (size_t)lane * 4;

    if (mode == 1) {               // final conv -> output, no LN
        *(float4*)(out + base) = t;
        return;
    }

    // residual
    float4 o = *(const float4*)(ori + base);
    t.x += o.x; t.y += o.y; t.z += o.z; t.w += o.w;

    float sum = t.x + t.y + t.z + t.w;
    float sq  = t.x * t.x + t.y * t.y + t.z * t.z + t.w * t.w;
    #pragma unroll
    for (int off = 16; off; off >>= 1) {
        sum += __shfl_xor_sync(0xFFFFFFFFu, sum, off);
        sq  += __shfl_xor_sync(0xFFFFFFFFu, sq,  off);
    }
    float mu  = sum * (1.0f / 128.0f);
    float var = sq * (1.0f / 128.0f) - mu * mu;
    float inv = rsqrtf(var + 1e-5f);

    float4 w   = *(const float4*)(lw + lane * 4);
    float4 lbv = *(const float4*)(lb + lane * 4);
    float4 u;
    u.x = fmaxf((t.x - mu) * inv * w.x + lbv.x, 0.f);
    u.y = fmaxf((t.y - mu) * inv * w.y + lbv.y, 0.f);
    u.z = fmaxf((t.z - mu) * inv * w.z + lbv.z, 0.f);
    u.w = fmaxf((t.w - mu) * inv * w.w + lbv.w, 0.f);
    *(float4*)(g_u + base) = u;
}

// ---------------------------------------------------------------------------
extern "C" void kernel_launch(void* const* d_in, const int* in_sizes, int n_in,
                              void* d_out, int out_size) {
    int iSrc, iDst, iW1, iB1, iW2, iB2, iL1w, iL1b, iL2w, iL2b;
    if (n_in >= 3 && in_sizes[1] == in_sizes[2] && in_sizes[1] > 100000) {
        iSrc = 1; iDst = 2; iW1 = 3; iB1 = 4; iW2 = 5; iB2 = 6;
        iL1w = 7; iL1b = 8; iL2w = 9; iL2b = 10;
    } else {
        iW1 = 1; iB1 = 2; iW2 = 3; iB2 = 4; iL1w = 5; iL1b = 6;
        iL2w = 7; iL2b = 8; iSrc = 9; iDst = 10;
    }

    const float* X   = (const float*)d_in[0];
    const int*   src = (const int*)d_in[iSrc];
    const int*   dst = (const int*)d_in[iDst];
    const float* W1  = (const float*)d_in[iW1];
    const float* b1  = (const float*)d_in[iB1];
    const float* W2  = (const float*)d_in[iW2];
    const float* b2  = (const float*)d_in[iB2];
    const float* l1w = (const float*)d_in[iL1w];
    const float* l1b = (const float*)d_in[iL1b];
    const float* l2w = (const float*)d_in[iL2w];
    const float* l2b = (const float*)d_in[iL2b];
    float* out = (float*)d_out;

    const int N = in_sizes[0] / D;
    const int E = in_sizes[iSrc];

    const int GEMM_SMEM = (128 * 128 + 64 * 132) * (int)sizeof(float); // 99328 B
    cudaFuncSetAttribute(k_gemm, cudaFuncAttributeMaxDynamicSharedMemorySize, GEMM_SMEM);

    const int T = 256;
    int zb = (N + T - 1) / T;
    int cb = (E + T - 1) / T;
    int gb = (N + 63) / 64;
    int wb = ((N * 32) + T - 1) / T;   // one warp per node

    // Build degree, dis, CSR (reused by all 3 convs)
    k_zero <<<zb, T>>>(N);
    k_count<<<cb, T>>>(dst, E);
    k_dis  <<<zb, T>>>(N);
    k_scan <<<1, 1024>>>(N);
    k_fill <<<cb, T>>>(src, dst, E);

    // conv 1 (W1, b1) + residual + LN1 + ReLU
    k_gemm  <<<gb, T, GEMM_SMEM>>>(X, W1, N, 0);
    k_gather<<<wb, T>>>(X, b1, l1w, l1b, out, N, 0);

    // conv 2 (W2, b2) + residual + LN2 + ReLU
    k_gemm  <<<gb, T, GEMM_SMEM>>>(X, W2, N, 1);
    k_gather<<<wb, T>>>(X, b2, l2w, l2b, out, N, 0);

    // conv 3 (W2, b2) -> output
    k_gemm  <<<gb, T, GEMM_SMEM>>>(X, W2, N, 1);
    k_gather<<<wb, T>>>(X, b2, l2w, l2b, out, N, 1);
}

// round 4
// speedup vs baseline: 1.5943x; 1.0220x over previous
#include <cuda_runtime.h>
#include <stdint.h>

#define D 128
#define NMAX 50000
#define EMAX 600000

// Scratch (static device globals). Referenced ONLY from device code.
__device__ __align__(16) float g_hs [(size_t)NMAX * D];  // (IN@W) * dis[row]
__device__ __align__(16) float g_u  [(size_t)NMAX * D];  // post-LN/ReLU activations
__device__ float g_dis[NMAX];
__device__ int   g_deg[NMAX];
__device__ int   g_cur[NMAX];
__device__ int   g_off[NMAX + 1];
__device__ int   g_bsum[64];
__device__ int   g_bsumx[64];
__device__ int   g_csr[EMAX];     // incoming-edge source ids, grouped by dst

// ---------------------------------------------------------------------------
__global__ void k_zero(int nN) {
    int i = blockIdx.x * blockDim.x + threadIdx.x;
    if (i < nN) { g_deg[i] = 0; g_cur[i] = 0; }
}

__global__ void k_count(const int* __restrict__ dst, int nE) {
    int e = blockIdx.x * blockDim.x + threadIdx.x;
    if (e < nE) atomicAdd(&g_deg[dst[e]], 1);
}

__global__ void k_dis(int nN) {
    int i = blockIdx.x * blockDim.x + threadIdx.x;
    if (i < nN) g_dis[i] = rsqrtf((float)g_deg[i] + 1.0f);
}

// ---- parallel exclusive scan of g_deg -> g_off (3 phases) ------------------
// Phase 1: per-block (1024 elems) exclusive scan + block totals
__global__ void __launch_bounds__(1024) k_scan1(int nN) {
    __shared__ int sh[1024];
    const int tid = threadIdx.x;
    const int gi = blockIdx.x * 1024 + tid;
    int v = (gi < nN) ? g_deg[gi] : 0;
    int val = v;
    sh[tid] = val;
    __syncthreads();
    #pragma unroll
    for (int off = 1; off < 1024; off <<= 1) {
        int t = (tid >= off) ? sh[tid - off] : 0;
        __syncthreads();
        val += t;
        sh[tid] = val;
        __syncthreads();
    }
    if (gi < nN) g_off[gi] = val - v;              // exclusive
    if (tid == 1023) g_bsum[blockIdx.x] = val;     // block total
}

// Phase 2: scan block totals (single small block)
__global__ void __launch_bounds__(64) k_scan2(int nBlocks, int nN) {
    __shared__ int sh[64];
    const int tid = threadIdx.x;
    int v = (tid < nBlocks) ? g_bsum[tid] : 0;
    int val = v;
    sh[tid] = val;
    __syncthreads();
    #pragma unroll
    for (int off = 1; off < 64; off <<= 1) {
        int t = (tid >= off) ? sh[tid - off] : 0;
        __syncthreads();
        val += t;
        sh[tid] = val;
        __syncthreads();
    }
    if (tid < nBlocks) g_bsumx[tid] = val - v;     // exclusive block offsets
    if (tid == 63) g_off[nN] = val;                // grand total
}

// Phase 3: add block offsets
__global__ void __launch_bounds__(1024) k_scan3(int nN) {
    int gi = blockIdx.x * 1024 + threadIdx.x;
    if (gi < nN) g_off[gi] += g_bsumx[blockIdx.x];
}

// Fill CSR: for each edge, append src into dst's row.
__global__ void k_fill(const int* __restrict__ src, const int* __restrict__ dst,
                       int nE) {
    int e = blockIdx.x * blockDim.x + threadIdx.x;
    if (e >= nE) return;
    int d = dst[e];
    int pos = atomicAdd(&g_cur[d], 1);
    g_csr[g_off[d] + pos] = src[e];
}

// ---------------------------------------------------------------------------
// GEMM v2: g_hs[r,:] = (IN[r,:] @ W) * g_dis[r],  IN = (useU ? g_u : Xext)
// 128 threads, block tile 64 rows x 128 cols, thread micro-tile 8x8,
// packed fma.rn.f32x2 accumulators (2 FMAs per issue slot).
// Smem: Ws 128x128 f32 (64KB) + Xd 64x128 duplicated float2 (64KB).
__global__ void __launch_bounds__(128) k_gemm(const float* __restrict__ Xext,
                                              const float* __restrict__ W,
                                              int nrows, int useU) {
    extern __shared__ float smem[];
    float*  Ws = smem;                        // 128*128 floats
    float2* Xd = (float2*)(smem + 128 * 128); // 64*128 float2 (dup pairs)

    const float* X = useU ? (const float*)g_u : Xext;
    const int tid = threadIdx.x;
    const int row0 = blockIdx.x * 64;

    // Load W: 4096 float4 / 128 threads = 32 each, coalesced
    {
        const float4* Wv = (const float4*)W;
        float4* Wsv = (float4*)Ws;
        #pragma unroll
        for (int i = 0; i < 32; i++) Wsv[tid + i * 128] = Wv[tid + i * 128];
    }
    // Load X tile (64 rows x 32 float4 = 2048 float4 / 128 = 16 each),
    // storing each scalar duplicated as {x,x} for packed-FMA A operand.
    {
        #pragma unroll
        for (int i = 0; i < 16; i++) {
            int idx = tid + i * 128;
            int r = idx >> 5;
            int c = idx & 31;
            float4 v = make_float4(0.f, 0.f, 0.f, 0.f);
            if (row0 + r < nrows) v = ((const float4*)(X + (size_t)(row0 + r) * D))[c];
            float2* p = &Xd[r * 128 + c * 4];
            p[0] = make_float2(v.x, v.x);
            p[1] = make_float2(v.y, v.y);
            p[2] = make_float2(v.z, v.z);
            p[3] = make_float2(v.w, v.w);
        }
    }
    __syncthreads();

    const int tx = tid & 15;   // cols tx*8 .. tx*8+7
    const int ty = tid >> 4;   // rows ty*8 .. ty*8+7

    unsigned long long acc[8][4];
    #pragma unroll
    for (int m = 0; m < 8; m++)
        #pragma unroll
        for (int j = 0; j < 4; j++) acc[m][j] = 0ull;

    const float2* xrow = &Xd[(ty * 8) * 128];

    #pragma unroll 4
    for (int k = 0; k < 128; k++) {
        // B: 8 cols = 2 LDS.128 = 4 packed pairs
        ulonglong2 b01 = *(const ulonglong2*)&Ws[k * 128 + tx * 8];
        ulonglong2 b23 = *(const ulonglong2*)&Ws[k * 128 + tx * 8 + 4];
        unsigned long long bp0 = b01.x, bp1 = b01.y, bp2 = b23.x, bp3 = b23.y;
        #pragma unroll
        for (int m = 0; m < 8; m++) {
            unsigned long long a = *(const unsigned long long*)&xrow[m * 128 + k];
            asm("fma.rn.f32x2 %0, %1, %2, %0;" : "+l"(acc[m][0]) : "l"(a), "l"(bp0));
            asm("fma.rn.f32x2 %0, %1, %2, %0;" : "+l"(acc[m][1]) : "l"(a), "l"(bp1));
            asm("fma.rn.f32x2 %0, %1, %2, %0;" : "+l"(acc[m][2]) : "l"(a), "l"(bp2));
            asm("fma.rn.f32x2 %0, %1, %2, %0;" : "+l"(acc[m][3]) : "l"(a), "l"(bp3));
        }
    }

    #pragma unroll
    for (int m = 0; m < 8; m++) {
        int r = row0 + ty * 8 + m;
        if (r < nrows) {
            float s = g_dis[r];
            union { unsigned long long u; float2 f; } c0, c1, c2, c3;
            c0.u = acc[m][0]; c1.u = acc[m][1]; c2.u = acc[m][2]; c3.u = acc[m][3];
            float4 v0 = make_float4(c0.f.x * s, c0.f.y * s, c1.f.x * s, c1.f.y * s);
            float4 v1 = make_float4(c2.f.x * s, c2.f.y * s, c3.f.x * s, c3.f.y * s);
            float* op = &g_hs[(size_t)r * D + tx * 8];
            *(float4*)op = v0;
            *(float4*)(op + 4) = v1;
        }
    }
}

// ---------------------------------------------------------------------------
// Fused gather + conv-finalize + (residual + LN + ReLU | plain output).
// One warp per node; lane owns 4 floats of the 128-wide row.
__global__ void __launch_bounds__(256) k_gather(const float* __restrict__ ori,
                                                const float* __restrict__ bias,
                                                const float* __restrict__ lw,
                                                const float* __restrict__ lb,
                                                float* __restrict__ out,
                                                int nN, int mode) {
    int idx = blockIdx.x * blockDim.x + threadIdx.x;
    int node = idx >> 5;
    if (node >= nN) return;
    const int lane = idx & 31;

    const int beg = g_off[node];
    const int end = g_off[node + 1];

    float4 a = make_float4(0.f, 0.f, 0.f, 0.f);
    const float4* hs4 = (const float4*)g_hs;

    int e = beg;
    for (; e + 1 < end; e += 2) {
        int s0 = __ldg(&g_csr[e]);
        int s1 = __ldg(&g_csr[e + 1]);
        float4 v0 = hs4[(size_t)s0 * 32 + lane];
        float4 v1 = hs4[(size_t)s1 * 32 + lane];
        a.x += v0.x; a.y += v0.y; a.z += v0.z; a.w += v0.w;
        a.x += v1.x; a.y += v1.y; a.z += v1.z; a.w += v1.w;
    }
    if (e < end) {
        int s0 = __ldg(&g_csr[e]);
        float4 v0 = hs4[(size_t)s0 * 32 + lane];
        a.x += v0.x; a.y += v0.y; a.z += v0.z; a.w += v0.w;
    }

    float4 hv = hs4[(size_t)node * 32 + lane];   // self-loop term
    float s = g_dis[node];
    float4 bb = *(const float4*)(bias + lane * 4);

    float4 t;
    t.x = s * (a.x + hv.x) + bb.x;
    t.y = s * (a.y + hv.y) + bb.y;
    t.z = s * (a.z + hv.z) + bb.z;
    t.w = s * (a.w + hv.w) + bb.w;

    size_t base = (size_t)node * D + (size_t)lane * 4;

    if (mode == 1) {               // final conv -> output, no LN
        *(float4*)(out + base) = t;
        return;
    }

    float4 o = *(const float4*)(ori + base);     // residual
    t.x += o.x; t.y += o.y; t.z += o.z; t.w += o.w;

    float sum = t.x + t.y + t.z + t.w;
    float sq  = t.x * t.x + t.y * t.y + t.z * t.z + t.w * t.w;
    #pragma unroll
    for (int off = 16; off; off >>= 1) {
        sum += __shfl_xor_sync(0xFFFFFFFFu, sum, off);
        sq  += __shfl_xor_sync(0xFFFFFFFFu, sq,  off);
    }
    float mu  = sum * (1.0f / 128.0f);
    float var = sq * (1.0f / 128.0f) - mu * mu;
    float inv = rsqrtf(var + 1e-5f);

    float4 w   = *(const float4*)(lw + lane * 4);
    float4 lbv = *(const float4*)(lb + lane * 4);
    float4 u;
    u.x = fmaxf((t.x - mu) * inv * w.x + lbv.x, 0.f);
    u.y = fmaxf((t.y - mu) * inv * w.y + lbv.y, 0.f);
    u.z = fmaxf((t.z - mu) * inv * w.z + lbv.z, 0.f);
    u.w = fmaxf((t.w - mu) * inv * w.w + lbv.w, 0.f);
    *(float4*)(g_u + base) = u;
}

// ---------------------------------------------------------------------------
extern "C" void kernel_launch(void* const* d_in, const int* in_sizes, int n_in,
                              void* d_out, int out_size) {
    int iSrc, iDst, iW1, iB1, iW2, iB2, iL1w, iL1b, iL2w, iL2b;
    if (n_in >= 3 && in_sizes[1] == in_sizes[2] && in_sizes[1] > 100000) {
        iSrc = 1; iDst = 2; iW1 = 3; iB1 = 4; iW2 = 5; iB2 = 6;
        iL1w = 7; iL1b = 8; iL2w = 9; iL2b = 10;
    } else {
        iW1 = 1; iB1 = 2; iW2 = 3; iB2 = 4; iL1w = 5; iL1b = 6;
        iL2w = 7; iL2b = 8; iSrc = 9; iDst = 10;
    }

    const float* X   = (const float*)d_in[0];
    const int*   src = (const int*)d_in[iSrc];
    const int*   dst = (const int*)d_in[iDst];
    const float* W1  = (const float*)d_in[iW1];
    const float* b1  = (const float*)d_in[iB1];
    const float* W2  = (const float*)d_in[iW2];
    const float* b2  = (const float*)d_in[iB2];
    const float* l1w = (const float*)d_in[iL1w];
    const float* l1b = (const float*)d_in[iL1b];
    const float* l2w = (const float*)d_in[iL2w];
    const float* l2b = (const float*)d_in[iL2b];
    float* out = (float*)d_out;

    const int N = in_sizes[0] / D;
    const int E = in_sizes[iSrc];

    const int GEMM_SMEM = (128 * 128) * 4 + (64 * 128) * 8;  // 64KB + 64KB
    cudaFuncSetAttribute(k_gemm, cudaFuncAttributeMaxDynamicSharedMemorySize, GEMM_SMEM);

    const int T = 256;
    int zb = (N + T - 1) / T;
    int cb = (E + T - 1) / T;
    int gb = (N + 63) / 64;
    int wb = ((N * 32) + T - 1) / T;        // one warp per node
    int sb = (N + 1023) / 1024;             // scan blocks (<=64)

    // Build degree, dis, CSR (reused by all 3 convs)
    k_zero <<<zb, T>>>(N);
    k_count<<<cb, T>>>(dst, E);
    k_dis  <<<zb, T>>>(N);
    k_scan1<<<sb, 1024>>>(N);
    k_scan2<<<1, 64>>>(sb, N);
    k_scan3<<<sb, 1024>>>(N);
    k_fill <<<cb, T>>>(src, dst, E);

    // conv 1 (W1, b1) + residual + LN1 + ReLU
    k_gemm  <<<gb, 128, GEMM_SMEM>>>(X, W1, N, 0);
    k_gather<<<wb, T>>>(X, b1, l1w, l1b, out, N, 0);

    // conv 2 (W2, b2) + residual + LN2 + ReLU
    k_gemm  <<<gb, 128, GEMM_SMEM>>>(X, W2, N, 1);
    k_gather<<<wb, T>>>(X, b2, l2w, l2b, out, N, 0);

    // conv 3 (W2, b2) -> output
    k_gemm  <<<gb, 128, GEMM_SMEM>>>(X, W2, N, 1);
    k_gather<<<wb, T>>>(X, b2, l2w, l2b, out, N, 1);
}

// round 6
// speedup vs baseline: 2.5367x; 1.5911x over previous
#include <cuda_runtime.h>
#include <cuda_bf16.h>
#include <stdint.h>

#define D 128
#define NMAX 50000
#define EMAX 600000
#define AS 264              // padded bf16 stride for smem tiles ([hi|lo] 256 + 8 pad)

// ---------------- scratch (static device globals) ---------------------------
__device__ __align__(16) float g_hs [(size_t)NMAX * D];
__device__ __align__(16) float g_u  [(size_t)NMAX * D];
__device__ float g_dis[NMAX];
__device__ int   g_deg[NMAX];
__device__ int   g_cur[NMAX];
__device__ int   g_off[NMAX + 1];
__device__ int   g_bsum[64];
__device__ int   g_bsumx[64];
__device__ int   g_csr[EMAX];
// Weight images: B[n][k] bf16, hi at k 0..127, lo at k 128..255, stride AS
__device__ __align__(16) __nv_bfloat16 g_WtA[128 * AS];
__device__ __align__(16) __nv_bfloat16 g_WtB[128 * AS];

// ---------------- helpers ----------------------------------------------------
__device__ __forceinline__ uint32_t smem_u32(const void* p) {
    uint32_t a;
    asm("{ .reg .u64 t; cvta.to.shared.u64 t, %1; cvt.u32.u64 %0, t; }"
        : "=r"(a) : "l"(p));
    return a;
}
__device__ __forceinline__ void ldmx4(uint32_t* r, uint32_t addr) {
    asm volatile("ldmatrix.sync.aligned.m8n8.x4.shared.b16 {%0,%1,%2,%3}, [%4];"
                 : "=r"(r[0]), "=r"(r[1]), "=r"(r[2]), "=r"(r[3]) : "r"(addr));
}
__device__ __forceinline__ void mma16816(float* c, const uint32_t* a,
                                         const uint32_t* b) {
    asm volatile(
        "mma.sync.aligned.m16n8k16.row.col.f32.bf16.bf16.f32 "
        "{%0,%1,%2,%3}, {%4,%5,%6,%7}, {%8,%9}, {%0,%1,%2,%3};"
        : "+f"(c[0]), "+f"(c[1]), "+f"(c[2]), "+f"(c[3])
        : "r"(a[0]), "r"(a[1]), "r"(a[2]), "r"(a[3]), "r"(b[0]), "r"(b[1]));
}

// ---------------- graph preprocessing ---------------------------------------
__global__ void k_zero(int nN) {
    int i = blockIdx.x * blockDim.x + threadIdx.x;
    if (i < nN) { g_deg[i] = 0; g_cur[i] = 0; }
}
__global__ void k_count(const int* __restrict__ dst, int nE) {
    int e = blockIdx.x * blockDim.x + threadIdx.x;
    if (e < nE) atomicAdd(&g_deg[dst[e]], 1);
}
__global__ void k_dis(int nN) {
    int i = blockIdx.x * blockDim.x + threadIdx.x;
    if (i < nN) g_dis[i] = rsqrtf((float)g_deg[i] + 1.0f);
}
__global__ void __launch_bounds__(1024) k_scan1(int nN) {
    __shared__ int sh[1024];
    const int tid = threadIdx.x;
    const int gi = blockIdx.x * 1024 + tid;
    int v = (gi < nN) ? g_deg[gi] : 0;
    int val = v;
    sh[tid] = val;
    __syncthreads();
    #pragma unroll
    for (int off = 1; off < 1024; off <<= 1) {
        int t = (tid >= off) ? sh[tid - off] : 0;
        __syncthreads();
        val += t; sh[tid] = val;
        __syncthreads();
    }
    if (gi < nN) g_off[gi] = val - v;
    if (tid == 1023) g_bsum[blockIdx.x] = val;
}
__global__ void __launch_bounds__(64) k_scan2(int nBlocks, int nN) {
    __shared__ int sh[64];
    const int tid = threadIdx.x;
    int v = (tid < nBlocks) ? g_bsum[tid] : 0;
    int val = v;
    sh[tid] = val;
    __syncthreads();
    #pragma unroll
    for (int off = 1; off < 64; off <<= 1) {
        int t = (tid >= off) ? sh[tid - off] : 0;
        __syncthreads();
        val += t; sh[tid] = val;
        __syncthreads();
    }
    if (tid < nBlocks) g_bsumx[tid] = val - v;
    if (tid == 63) g_off[nN] = val;
}
__global__ void __launch_bounds__(1024) k_scan3(int nN) {
    int gi = blockIdx.x * 1024 + threadIdx.x;
    if (gi < nN) g_off[gi] += g_bsumx[blockIdx.x];
}
__global__ void k_fill(const int* __restrict__ src, const int* __restrict__ dst,
                       int nE) {
    int e = blockIdx.x * blockDim.x + threadIdx.x;
    if (e >= nE) return;
    int d = dst[e];
    int pos = atomicAdd(&g_cur[d], 1);
    g_csr[g_off[d] + pos] = src[e];
}

// ---------------- weight prep: W[k][n] -> B[n][k] split bf16 -----------------
__global__ void k_prep(const float* __restrict__ W, int which) {
    __nv_bfloat16* img = which ? g_WtB : g_WtA;
    int i = blockIdx.x * blockDim.x + threadIdx.x;
    if (i >= D * D) return;
    int k = i >> 7, n = i & 127;
    float x = W[k * D + n];
    __nv_bfloat16 hi = __float2bfloat16(x);
    __nv_bfloat16 lo = __float2bfloat16(x - __bfloat162float(hi));
    img[n * AS + k]       = hi;
    img[n * AS + 128 + k] = lo;
}

// ---------------- warp-MMA GEMM: g_hs[r,:] = (IN[r,:] @ W) * dis[r] ----------
// 256 threads; block tile 128x128; warp tile 32x64 (4x2 warps);
// 24 K-steps of m16n8k16 over split-bf16 [hi|lo] operands.
__global__ void __launch_bounds__(256) k_gemm_mma(const float* __restrict__ Xext,
                                                  int useU, int whichW,
                                                  int nrows) {
    extern __shared__ __align__(16) __nv_bfloat16 sm[];
    __nv_bfloat16* Asm = sm;              // 128 x AS
    __nv_bfloat16* Bsm = sm + 128 * AS;   // 128 x AS

    const float* X = useU ? (const float*)g_u : Xext;
    const __nv_bfloat16* Wimg = whichW ? g_WtB : g_WtA;

    const int tid = threadIdx.x;
    const int wid = tid >> 5;
    const int lane = tid & 31;
    const int row0 = blockIdx.x * 128;

    // Copy weight image: 128*AS bf16 = 67584 B = 4224 float4
    {
        const float4* src = (const float4*)Wimg;
        float4* dst = (float4*)Bsm;
        #pragma unroll
        for (int i = 0; i < 17; i++) {
            int idx = tid + i * 256;
            if (idx < (128 * AS * 2) / 16) dst[idx] = src[idx];
        }
    }
    // A: load f32 rows, split hi/lo, store [hi|lo] padded
    {
        #pragma unroll
        for (int i = 0; i < 16; i++) {
            int idx = tid + i * 256;
            int r = idx >> 5;        // row in tile
            int c4 = idx & 31;       // float4 col
            float4 v = make_float4(0.f, 0.f, 0.f, 0.f);
            if (row0 + r < nrows)
                v = ((const float4*)(X + (size_t)(row0 + r) * D))[c4];
            int k = c4 * 4;
            __nv_bfloat16 hx = __float2bfloat16(v.x);
            __nv_bfloat16 hy = __float2bfloat16(v.y);
            __nv_bfloat16 hz = __float2bfloat16(v.z);
            __nv_bfloat16 hw = __float2bfloat16(v.w);
            __nv_bfloat16* ap = Asm + r * AS + k;
            *(__nv_bfloat162*)(ap)     = __halves2bfloat162(hx, hy);
            *(__nv_bfloat162*)(ap + 2) = __halves2bfloat162(hz, hw);
            __nv_bfloat162 lo01 = __floats2bfloat162_rn(
                v.x - __bfloat162float(hx), v.y - __bfloat162float(hy));
            __nv_bfloat162 lo23 = __floats2bfloat162_rn(
                v.z - __bfloat162float(hz), v.w - __bfloat162float(hw));
            *(__nv_bfloat162*)(ap + 128)     = lo01;
            *(__nv_bfloat162*)(ap + 128 + 2) = lo23;
        }
    }
    __syncthreads();

    const int warp_m = wid & 3;          // 4 warps along M (32 rows each)
    const int warp_n = wid >> 2;         // 2 warps along N (64 cols each)

    // ldmatrix lane addressing
    const int rowA = warp_m * 32 + (lane & 15);
    const int kAo  = (lane & 16) ? 8 : 0;
    const uint32_t aBase = smem_u32(Asm) + (uint32_t)(rowA * AS + kAo) * 2;
    const int nB   = warp_n * 64 + (lane & 7) + ((lane & 16) ? 8 : 0);
    const int kBo  = (lane & 8) ? 8 : 0;
    const uint32_t bBase = smem_u32(Bsm) + (uint32_t)(nB * AS + kBo) * 2;

    float acc[2][8][4];
    #pragma unroll
    for (int mt = 0; mt < 2; mt++)
        #pragma unroll
        for (int nt = 0; nt < 8; nt++)
            #pragma unroll
            for (int q = 0; q < 4; q++) acc[mt][nt][q] = 0.f;

    #pragma unroll
    for (int j = 0; j < 24; j++) {
        const int seg = j >> 3;
        const int o = (j & 7) * 16;
        const int ka = ((seg == 1) ? 128 : 0) + o;   // A: hi, lo, hi
        const int kb = ((seg == 2) ? 128 : 0) + o;   // B: hi, hi, lo

        uint32_t a[2][4];
        #pragma unroll
        for (int mt = 0; mt < 2; mt++)
            ldmx4(a[mt], aBase + (uint32_t)(mt * 16 * AS + ka) * 2);

        uint32_t b[8][2];
        #pragma unroll
        for (int p = 0; p < 4; p++) {
            uint32_t r[4];
            ldmx4(r, bBase + (uint32_t)(p * 16 * AS + kb) * 2);
            b[p * 2][0] = r[0]; b[p * 2][1] = r[1];
            b[p * 2 + 1][0] = r[2]; b[p * 2 + 1][1] = r[3];
        }

        #pragma unroll
        for (int mt = 0; mt < 2; mt++)
            #pragma unroll
            for (int nt = 0; nt < 8; nt++)
                mma16816(acc[mt][nt], a[mt], b[nt]);
    }

    // Epilogue: scale by dis[row], store float2 pairs
    #pragma unroll
    for (int mt = 0; mt < 2; mt++) {
        int rlo = row0 + warp_m * 32 + mt * 16 + (lane >> 2);
        int rhi = rlo + 8;
        float slo = (rlo < nrows) ? g_dis[rlo] : 0.f;
        float shi = (rhi < nrows) ? g_dis[rhi] : 0.f;
        #pragma unroll
        for (int nt = 0; nt < 8; nt++) {
            int col = warp_n * 64 + nt * 8 + 2 * (lane & 3);
            if (rlo < nrows)
                *(float2*)&g_hs[(size_t)rlo * D + col] =
                    make_float2(acc[mt][nt][0] * slo, acc[mt][nt][1] * slo);
            if (rhi < nrows)
                *(float2*)&g_hs[(size_t)rhi * D + col] =
                    make_float2(acc[mt][nt][2] * shi, acc[mt][nt][3] * shi);
        }
    }
}

// ---------------- fused gather + finalize (+LN+ReLU | output) ---------------
__global__ void __launch_bounds__(256) k_gather(const float* __restrict__ ori,
                                                const float* __restrict__ bias,
                                                const float* __restrict__ lw,
                                                const float* __restrict__ lb,
                                                float* __restrict__ out,
                                                int nN, int mode) {
    int idx = blockIdx.x * blockDim.x + threadIdx.x;
    int node = idx >> 5;
    if (node >= nN) return;
    const int lane = idx & 31;

    const int beg = g_off[node];
    const int end = g_off[node + 1];

    float4 a = make_float4(0.f, 0.f, 0.f, 0.f);
    const float4* hs4 = (const float4*)g_hs;

    int e = beg;
    for (; e + 1 < end; e += 2) {
        int s0 = __ldg(&g_csr[e]);
        int s1 = __ldg(&g_csr[e + 1]);
        float4 v0 = hs4[(size_t)s0 * 32 + lane];
        float4 v1 = hs4[(size_t)s1 * 32 + lane];
        a.x += v0.x; a.y += v0.y; a.z += v0.z; a.w += v0.w;
        a.x += v1.x; a.y += v1.y; a.z += v1.z; a.w += v1.w;
    }
    if (e < end) {
        int s0 = __ldg(&g_csr[e]);
        float4 v0 = hs4[(size_t)s0 * 32 + lane];
        a.x += v0.x; a.y += v0.y; a.z += v0.z; a.w += v0.w;
    }

    float4 hv = hs4[(size_t)node * 32 + lane];
    float s = g_dis[node];
    float4 bb = *(const float4*)(bias + lane * 4);

    float4 t;
    t.x = s * (a.x + hv.x) + bb.x;
    t.y = s * (a.y + hv.y) + bb.y;
    t.z = s * (a.z + hv.z) + bb.z;
    t.w = s * (a.w + hv.w) + bb.w;

    size_t base = (size_t)node * D + (size_t)lane * 4;

    if (mode == 1) {
        *(float4*)(out + base) = t;
        return;
    }

    float4 o = *(const float4*)(ori + base);
    t.x += o.x; t.y += o.y; t.z += o.z; t.w += o.w;

    float sum = t.x + t.y + t.z + t.w;
    float sq  = t.x * t.x + t.y * t.y + t.z * t.z + t.w * t.w;
    #pragma unroll
    for (int off = 16; off; off >>= 1) {
        sum += __shfl_xor_sync(0xFFFFFFFFu, sum, off);
        sq  += __shfl_xor_sync(0xFFFFFFFFu, sq,  off);
    }
    float mu  = sum * (1.0f / 128.0f);
    float var = sq * (1.0f / 128.0f) - mu * mu;
    float inv = rsqrtf(var + 1e-5f);

    float4 w   = *(const float4*)(lw + lane * 4);
    float4 lbv = *(const float4*)(lb + lane * 4);
    float4 u;
    u.x = fmaxf((t.x - mu) * inv * w.x + lbv.x, 0.f);
    u.y = fmaxf((t.y - mu) * inv * w.y + lbv.y, 0.f);
    u.z = fmaxf((t.z - mu) * inv * w.z + lbv.z, 0.f);
    u.w = fmaxf((t.w - mu) * inv * w.w + lbv.w, 0.f);
    *(float4*)(g_u + base) = u;
}

// ---------------------------------------------------------------------------
extern "C" void kernel_launch(void* const* d_in, const int* in_sizes, int n_in,
                              void* d_out, int out_size) {
    int iSrc, iDst, iW1, iB1, iW2, iB2, iL1w, iL1b, iL2w, iL2b;
    if (n_in >= 3 && in_sizes[1] == in_sizes[2] && in_sizes[1] > 100000) {
        iSrc = 1; iDst = 2; iW1 = 3; iB1 = 4; iW2 = 5; iB2 = 6;
        iL1w = 7; iL1b = 8; iL2w = 9; iL2b = 10;
    } else {
        iW1 = 1; iB1 = 2; iW2 = 3; iB2 = 4; iL1w = 5; iL1b = 6;
        iL2w = 7; iL2b = 8; iSrc = 9; iDst = 10;
    }

    const float* X   = (const float*)d_in[0];
    const int*   src = (const int*)d_in[iSrc];
    const int*   dst = (const int*)d_in[iDst];
    const float* W1  = (const float*)d_in[iW1];
    const float* b1  = (const float*)d_in[iB1];
    const float* W2  = (const float*)d_in[iW2];
    const float* b2  = (const float*)d_in[iB2];
    const float* l1w = (const float*)d_in[iL1w];
    const float* l1b = (const float*)d_in[iL1b];
    const float* l2w = (const float*)d_in[iL2w];
    const float* l2b = (const float*)d_in[iL2b];
    float* out = (float*)d_out;

    const int N = in_sizes[0] / D;
    const int E = in_sizes[iSrc];

    const int MMA_SMEM = 2 * 128 * AS * 2;  // 135168 B
    cudaFuncSetAttribute(k_gemm_mma, cudaFuncAttributeMaxDynamicSharedMemorySize,
                         MMA_SMEM);

    const int T = 256;
    int zb = (N + T - 1) / T;
    int cb = (E + T - 1) / T;
    int gb = (N + 127) / 128;
    int wb = ((N * 32) + T - 1) / T;
    int sb = (N + 1023) / 1024;

    // graph preprocessing + weight prep
    k_zero <<<zb, T>>>(N);
    k_count<<<cb, T>>>(dst, E);
    k_dis  <<<zb, T>>>(N);
    k_scan1<<<sb, 1024>>>(N);
    k_scan2<<<1, 64>>>(sb, N);
    k_scan3<<<sb, 1024>>>(N);
    k_fill <<<cb, T>>>(src, dst, E);
    k_prep <<<64, 256>>>(W1, 0);
    k_prep <<<64, 256>>>(W2, 1);

    // conv 1 (W1, b1) + residual + LN1 + ReLU
    k_gemm_mma<<<gb, T, MMA_SMEM>>>(X, 0, 0, N);
    k_gather  <<<wb, T>>>(X, b1, l1w, l1b, out, N, 0);

    // conv 2 (W2, b2) + residual + LN2 + ReLU
    k_gemm_mma<<<gb, T, MMA_SMEM>>>(X, 1, 1, N);
    k_gather  <<<wb, T>>>(X, b2, l2w, l2b, out, N, 0);

    // conv 3 (W2, b2) -> output
    k_gemm_mma<<<gb, T, MMA_SMEM>>>(X, 1, 1, N);
    k_gather  <<<wb, T>>>(X, b2, l2w, l2b, out, N, 1);
}